// round 15
// baseline (speedup 1.0000x reference)
#include <cuda_runtime.h>
#include <cuda_bf16.h>
#include <cuda_fp16.h>
#include <cstdint>
#include <math.h>

#define DIMS 256
#define KCODES 1024
#define NROWS_MAX 65536
#define BM 128
#define BN 128
#define NHALF (KCODES / 2)                // codes per CTA (code-split 2)
#define NTHREADS 512
#define MARGIN 0.25f

#define A_ROW_B 528                       // 256 fp16 data (512B) + 16 pad
#define A_BYTES (BM * A_ROW_B)            // 67584
#define B_ROW_B 144                       // 64 fp16 data (128B) + 16 pad
#define B_CHUNKB (BN * B_ROW_B)           // 18432
#define DSMEM_BYTES (A_BYTES + 2 * B_CHUNKB + 1024)

typedef unsigned int u32;

__device__ float d_cnorm[KCODES];
__device__ float d_counts[KCODES];
__device__ __half d_cbh[KCODES * 256];    // fp16 codebook
__device__ int d_idx[NROWS_MAX];
__device__ int d_flagList[NROWS_MAX];
__device__ int d_flagCount;
// per-(half, row) partial top-2
__device__ float d_pb1[2][NROWS_MAX];
__device__ float d_pb2[2][NROWS_MAX];
__device__ int   d_pi[2][NROWS_MAX];

// ---------------- helpers ----------------
__device__ __forceinline__ u32 smem_u32(const void* p) {
    u32 a;
    asm("{ .reg .u64 t; cvta.to.shared.u64 t, %1; cvt.u32.u64 %0, t; }"
        : "=r"(a) : "l"(p));
    return a;
}
__device__ __forceinline__ void cpasync16(u32 dst, const void* src) {
    asm volatile("cp.async.cg.shared.global [%0], [%1], 16;"
                 :: "r"(dst), "l"(src) : "memory");
}
__device__ __forceinline__ void cp_commit() {
    asm volatile("cp.async.commit_group;" ::: "memory");
}
__device__ __forceinline__ void cp_wait0() {
    asm volatile("cp.async.wait_group 0;" ::: "memory");
}
__device__ __forceinline__ void mma_f16(float* c, const u32* a, u32 b0, u32 b1) {
    asm volatile(
        "mma.sync.aligned.m16n8k16.row.col.f32.f16.f16.f32 "
        "{%0,%1,%2,%3}, {%4,%5,%6,%7}, {%8,%9}, {%0,%1,%2,%3};"
        : "+f"(c[0]), "+f"(c[1]), "+f"(c[2]), "+f"(c[3])
        : "r"(a[0]), "r"(a[1]), "r"(a[2]), "r"(a[3]), "r"(b0), "r"(b1));
}
__device__ __forceinline__ void ldsm_x4(u32& r0, u32& r1, u32& r2, u32& r3, u32 a) {
    asm volatile("ldmatrix.sync.aligned.m8n8.x4.shared.b16 {%0,%1,%2,%3}, [%4];"
        : "=r"(r0), "=r"(r1), "=r"(r2), "=r"(r3) : "r"(a));
}

// ---------------------------------------------------------------------------
// prep: zero counts/flags, ||c||^2 (fp32), codebook -> fp16
// ---------------------------------------------------------------------------
__global__ void prep_kernel(const float* __restrict__ cb) {
    int gtid = blockIdx.x * blockDim.x + threadIdx.x;
    if (gtid < KCODES) d_counts[gtid] = 0.0f;
    if (gtid == 0) d_flagCount = 0;
    int w = gtid >> 5;
    int lane = threadIdx.x & 31;
    if (w < KCODES) {
        const float* r = cb + (size_t)w * DIMS;
        float s = 0.0f;
        #pragma unroll
        for (int i = 0; i < DIMS / 32; i++) {
            int d = lane + i * 32;
            float v = r[d];
            s = fmaf(v, v, s);
            d_cbh[(size_t)w * DIMS + d] = __float2half(v);
        }
        #pragma unroll
        for (int off = 16; off > 0; off >>= 1)
            s += __shfl_xor_sync(0xFFFFFFFFu, s, off);
        if (lane == 0) d_cnorm[w] = s;
    }
}

// ---------------------------------------------------------------------------
// main: fp16 HMMA GEMM, code-split x2 (each CTA: 128 rows x 512 codes)
// ---------------------------------------------------------------------------
__global__ __launch_bounds__(NTHREADS, 1)
void vq_kernel(const float* __restrict__ z) {
    extern __shared__ char raw[];
    char* dsm = (char*)(((uintptr_t)raw + 1023) & ~(uintptr_t)1023);
    char* Ab = dsm;                         // 66 KB z fp16, resident
    char* Bb = dsm + A_BYTES;               // 2 x 18 KB B buffers
    float* redV1 = (float*)Bb;              // aliases B bufs post-GEMM
    float* redV2 = redV1 + BM * 16;
    int*   redI  = (int*)(redV2 + BM * 16);

    const int tid = threadIdx.x;
    const int lane = tid & 31;
    const int wid = tid >> 5;               // 0..15
    const int warpRow = wid & 3;            // 4 row-warps x 32 rows
    const int warpCol = wid >> 2;           // 4 col-warps x 32 cols
    const int g = lane >> 2;                // 0..7
    const int tig = lane & 3;               // 0..3
    const int half = blockIdx.x & 1;
    const int rowBase = (blockIdx.x >> 1) * BM;
    const int codeBase = half * NHALF;
    const u32 A_u32 = smem_u32(Ab);
    const u32 B_u32 = smem_u32(Bb);

    // ---- build A: z -> fp16, coalesced float2 loads ----
    for (int i = tid; i < BM * 128; i += NTHREADS) {
        int r = i >> 7, d2 = i & 127;
        float2 f = ((const float2*)(z + (size_t)(rowBase + r) * DIMS))[d2];
        __half h0 = __float2half(f.x);
        __half h1 = __float2half(f.y);
        u32 uh = (u32)__half_as_ushort(h0) | ((u32)__half_as_ushort(h1) << 16);
        *(u32*)(Ab + r * A_ROW_B + d2 * 4) = uh;
    }
    __syncthreads();

    float best1[4], best2[4];
    int idx1[4];
    #pragma unroll
    for (int i = 0; i < 4; i++) { best1[i] = 3.4e38f; best2[i] = 3.4e38f; idx1[i] = 0; }

    // ldmatrix lane-address bases
    const u32 aLane = A_u32 + (warpRow * 32 + (lane & 15)) * A_ROW_B
                            + ((lane & 16) ? 16 : 0);
    const u32 bLane = B_u32 + (warpCol * 32 + (lane & 7) + ((lane & 16) ? 8 : 0)) * B_ROW_B
                            + ((lane & 8) ? 16 : 0);

    // B loader: tid -> (code row, 32B quarter)
    const int bRow = tid >> 2;
    const int part = tid & 3;

    for (int chnk = 0; chnk < NHALF / BN; chnk++) {
        float acc[2][4][4];
        #pragma unroll
        for (int mf = 0; mf < 2; mf++)
            #pragma unroll
            for (int nf = 0; nf < 4; nf++)
                #pragma unroll
                for (int q = 0; q < 4; q++) acc[mf][nf][q] = 0.0f;

        const __half* gRow = d_cbh
            + (size_t)(codeBase + chnk * BN + bRow) * DIMS + part * 16;
        const u32 dstBase = B_u32 + bRow * B_ROW_B + part * 32;

        // prologue: issue step 0 -> buf0
        cpasync16(dstBase, gRow);
        cpasync16(dstBase + 16, gRow + 8);
        cp_commit();

        #pragma unroll
        for (int s = 0; s < 4; s++) {
            cp_wait0();
            __syncthreads();
            if (s < 3) {
                const __half* src = gRow + (s + 1) * 64;
                u32 dst = dstBase + (((s + 1) & 1) ? B_CHUNKB : 0);
                cpasync16(dst, src);
                cpasync16(dst + 16, src + 8);
                cp_commit();
            }
            const u32 aS = aLane + s * 128;                    // +64 fp16
            const u32 bS = bLane + ((s & 1) ? B_CHUNKB : 0);
            #pragma unroll
            for (int kk = 0; kk < 4; kk++) {
                u32 a0[4], a1[4], bA[4], bB[4];
                ldsm_x4(a0[0], a0[1], a0[2], a0[3], aS + kk * 32);
                ldsm_x4(a1[0], a1[1], a1[2], a1[3], aS + 16 * A_ROW_B + kk * 32);
                ldsm_x4(bA[0], bA[1], bA[2], bA[3], bS + kk * 32);
                ldsm_x4(bB[0], bB[1], bB[2], bB[3], bS + 16 * B_ROW_B + kk * 32);
                mma_f16(acc[0][0], a0, bA[0], bA[1]);
                mma_f16(acc[1][0], a1, bA[0], bA[1]);
                mma_f16(acc[0][1], a0, bA[2], bA[3]);
                mma_f16(acc[1][1], a1, bA[2], bA[3]);
                mma_f16(acc[0][2], a0, bB[0], bB[1]);
                mma_f16(acc[1][2], a1, bB[0], bB[1]);
                mma_f16(acc[0][3], a0, bB[2], bB[3]);
                mma_f16(acc[1][3], a1, bB[2], bB[3]);
            }
        }

        // fold chunk into per-row top-2: cost = ||c||^2 - 2*dot
        #pragma unroll
        for (int nf = 0; nf < 4; nf++) {
            #pragma unroll
            for (int cc = 0; cc < 2; cc++) {
                int col = codeBase + chnk * BN + warpCol * 32 + nf * 8 + tig * 2 + cc;
                float cn = __ldg(&d_cnorm[col]);
                #pragma unroll
                for (int mf = 0; mf < 2; mf++) {
                    #pragma unroll
                    for (int sub = 0; sub < 2; sub++) {
                        float cost = fmaf(-2.0f, acc[mf][nf][sub * 2 + cc], cn);
                        int rr = mf * 2 + sub;
                        if (cost < best1[rr]) {
                            best2[rr] = best1[rr];
                            best1[rr] = cost; idx1[rr] = col;
                        } else if (cost < best2[rr]) {
                            best2[rr] = cost;
                        }
                    }
                }
            }
        }
    }

    __syncthreads();   // GEMM reads of B buffers done; alias as reduction

    const int slot = warpCol * 4 + tig;   // 16 candidates per row
    #pragma unroll
    for (int rr = 0; rr < 4; rr++) {
        int r = warpRow * 32 + (rr >> 1) * 16 + (rr & 1) * 8 + g;
        redV1[r * 16 + slot] = best1[rr];
        redV2[r * 16 + slot] = best2[rr];
        redI[r * 16 + slot] = idx1[rr];
    }
    __syncthreads();

    if (tid < BM) {
        float b1 = 3.4e38f, b2 = 3.4e38f;
        int i1 = 0x7FFFFFFF;
        #pragma unroll
        for (int t = 0; t < 16; t++) {
            float v1 = redV1[tid * 16 + t];
            float v2 = redV2[tid * 16 + t];
            int ix = redI[tid * 16 + t];
            if (v1 < b1) {
                b2 = fminf(b1, v2);
                b1 = v1; i1 = ix;
            } else if (v1 == b1) {
                i1 = min(i1, ix);
                b2 = fminf(b2, v2);
            } else {
                b2 = fminf(b2, fminf(v1, v2));
            }
        }
        d_pb1[half][rowBase + tid] = b1;
        d_pb2[half][rowBase + tid] = b2;
        d_pi[half][rowBase + tid] = i1;
    }
}

// ---------------------------------------------------------------------------
// merge: combine two half-codebook candidates, flag, histogram, gather
// ---------------------------------------------------------------------------
__global__ void merge_kernel(const float* __restrict__ cb,
                             float* __restrict__ out) {
    __shared__ int sIdx[256];
    const int tid = threadIdx.x;
    const int row = blockIdx.x * 256 + tid;

    float b1a = d_pb1[0][row], b2a = d_pb2[0][row];
    float b1b = d_pb1[1][row], b2b = d_pb2[1][row];
    int i1a = d_pi[0][row], i1b = d_pi[1][row];

    float b1, b2;
    int i1;
    if (b1a <= b1b) {           // half A indices < half B: ties -> A (lower idx)
        b1 = b1a; i1 = i1a; b2 = fminf(b2a, b1b);
    } else {
        b1 = b1b; i1 = i1b; b2 = fminf(b2b, b1a);
    }
    d_idx[row] = i1;
    sIdx[tid] = i1;
    atomicAdd(&d_counts[i1], 1.0f);
    if (b2 - b1 < MARGIN) {
        int p = atomicAdd(&d_flagCount, 1);
        d_flagList[p] = row;
    }
    __syncthreads();

    const float4* cb4 = (const float4*)cb;
    float4* out4 = (float4*)out;
    const int rowBase = blockIdx.x * 256;
    for (int i = tid; i < 256 * 64; i += 256) {
        int r = i >> 6, q = i & 63;
        out4[(size_t)(rowBase + r) * 64 + q] = cb4[(size_t)sIdx[r] * 64 + q];
    }
}

// ---------------------------------------------------------------------------
// rescan: exact fp32 scan for ambiguous rows, 16 rows per block-iteration
// ---------------------------------------------------------------------------
__global__ void rescan_kernel(const float* __restrict__ z,
                              const float* __restrict__ cb,
                              float* __restrict__ out) {
    __shared__ float zr[16][DIMS];
    __shared__ float sRV[16][8];
    __shared__ int   sRI[16][8];
    __shared__ int   sRow[16];
    __shared__ int   sFix[16];

    const int tid = threadIdx.x;
    const int lane = tid & 31;
    const int wrp = tid >> 5;
    const int cnt = d_flagCount;

    for (int base = blockIdx.x * 16; base < cnt; base += gridDim.x * 16) {
        const int nr = min(16, cnt - base);
        for (int i = tid; i < 16 * DIMS; i += 256)
            ((float*)zr)[i] = 0.0f;
        __syncthreads();
        if (tid < nr) sRow[tid] = d_flagList[base + tid];
        __syncthreads();
        for (int i = tid; i < nr * DIMS; i += 256)
            zr[i >> 8][i & 255] = z[(size_t)sRow[i >> 8] * DIMS + (i & 255)];
        __syncthreads();

        float bb[16]; int bi[16];
        #pragma unroll
        for (int r = 0; r < 16; r++) { bb[r] = 3.4e38f; bi[r] = 0x7FFFFFFF; }

        #pragma unroll
        for (int cc = 0; cc < 4; cc++) {
            const int c = tid + cc * 256;
            const float4* cp = (const float4*)(cb + (size_t)c * DIMS);
            #pragma unroll
            for (int pass = 0; pass < 2; pass++) {
                float dot[8];
                #pragma unroll
                for (int r = 0; r < 8; r++) dot[r] = 0.0f;
                for (int q = 0; q < 64; q++) {
                    float4 cv = cp[q];
                    #pragma unroll
                    for (int r = 0; r < 8; r++) {
                        float4 zv = *(const float4*)&zr[pass * 8 + r][q * 4];
                        dot[r] = fmaf(zv.x, cv.x, dot[r]);
                        dot[r] = fmaf(zv.y, cv.y, dot[r]);
                        dot[r] = fmaf(zv.z, cv.z, dot[r]);
                        dot[r] = fmaf(zv.w, cv.w, dot[r]);
                    }
                }
                float cn = __ldg(&d_cnorm[c]);
                #pragma unroll
                for (int r = 0; r < 8; r++) {
                    float cost = fmaf(-2.0f, dot[r], cn);
                    int rr = pass * 8 + r;
                    if (cost < bb[rr] || (cost == bb[rr] && c < bi[rr])) {
                        bb[rr] = cost; bi[rr] = c;
                    }
                }
            }
        }
        #pragma unroll
        for (int off = 16; off > 0; off >>= 1) {
            #pragma unroll
            for (int r = 0; r < 16; r++) {
                float vv = __shfl_xor_sync(0xFFFFFFFFu, bb[r], off);
                int ii = __shfl_xor_sync(0xFFFFFFFFu, bi[r], off);
                if (vv < bb[r] || (vv == bb[r] && ii < bi[r])) { bb[r] = vv; bi[r] = ii; }
            }
        }
        if (lane == 0) {
            #pragma unroll
            for (int r = 0; r < 16; r++) { sRV[r][wrp] = bb[r]; sRI[r][wrp] = bi[r]; }
        }
        __syncthreads();
        if (tid < nr) {
            float bv = 3.4e38f; int bix = 0x7FFFFFFF;
            #pragma unroll
            for (int w = 0; w < 8; w++) {
                float v = sRV[tid][w]; int ix = sRI[tid][w];
                if (v < bv || (v == bv && ix < bix)) { bv = v; bix = ix; }
            }
            int old = d_idx[sRow[tid]];
            sFix[tid] = bix;
            if (bix != old) {
                d_idx[sRow[tid]] = bix;
                atomicAdd(&d_counts[old], -1.0f);
                atomicAdd(&d_counts[bix], 1.0f);
            }
        }
        __syncthreads();
        const float4* cb4 = (const float4*)cb;
        float4* out4 = (float4*)out;
        for (int i = tid; i < nr * 64; i += 256) {
            int r = i >> 6, q = i & 63;
            out4[(size_t)sRow[r] * 64 + q] = cb4[(size_t)sFix[r] * 64 + q];
        }
        __syncthreads();
    }
}

// ---------------------------------------------------------------------------
__global__ void perp_kernel(float* __restrict__ out, int nd, float n) {
    __shared__ float s[KCODES];
    int t = threadIdx.x;
    float e = d_counts[t] / n;
    s[t] = e * logf(e + 1e-10f);
    __syncthreads();
    for (int st = KCODES / 2; st > 0; st >>= 1) {
        if (t < st) s[t] += s[t + st];
        __syncthreads();
    }
    if (t == 0) {
        out[nd] = 0.0f;
        out[nd + 1] = expf(-s[0]);
    }
}

extern "C" void kernel_launch(void* const* d_in, const int* in_sizes, int n_in,
                              void* d_out, int out_size) {
    const float* z = (const float*)d_in[0];
    const float* cb = (const float*)d_in[1];
    float* out = (float*)d_out;

    int nrows = in_sizes[0] / DIMS;  // 65536
    cudaFuncSetAttribute(vq_kernel, cudaFuncAttributeMaxDynamicSharedMemorySize,
                         DSMEM_BYTES);
    prep_kernel<<<128, 256>>>(cb);
    vq_kernel<<<(nrows / BM) * 2, NTHREADS, DSMEM_BYTES>>>(z);
    merge_kernel<<<nrows / 256, 256>>>(cb, out);
    rescan_kernel<<<256, 256>>>(z, cb, out);
    long nd = (long)nrows * DIMS;
    if ((long)out_size >= nd + 2)
        perp_kernel<<<1, KCODES>>>(out, (int)nd, (float)nrows);
}

// round 16
// speedup vs baseline: 1.1087x; 1.1087x over previous
#include <cuda_runtime.h>
#include <cuda_bf16.h>
#include <cuda_fp16.h>
#include <cstdint>
#include <math.h>

#define DIMS 256
#define KCODES 1024
#define NROWS_MAX 65536
#define BM 128
#define BN 128
#define NTHREADS 512
#define MARGIN 0.25f

#define A_ROW_B 528                       // 256 fp16 data (512B) + 16 pad
#define A_BYTES (BM * A_ROW_B)            // 67584
#define B_ROW_B 144                       // 64 fp16 data (128B) + 16 pad
#define B_CHUNKB (BN * B_ROW_B)           // 18432
#define DSMEM_BYTES (A_BYTES + 2 * B_CHUNKB + 1024)

typedef unsigned int u32;

__device__ float d_cnorm[KCODES];
__device__ float d_counts[KCODES];
__device__ __half d_cbh[KCODES * 256];    // fp16 codebook
__device__ int d_idx[NROWS_MAX];
__device__ int d_flagList[NROWS_MAX];
__device__ int d_flagCount;

// ---------------- helpers ----------------
__device__ __forceinline__ u32 smem_u32(const void* p) {
    u32 a;
    asm("{ .reg .u64 t; cvta.to.shared.u64 t, %1; cvt.u32.u64 %0, t; }"
        : "=r"(a) : "l"(p));
    return a;
}
__device__ __forceinline__ void cpasync16(u32 dst, const void* src) {
    asm volatile("cp.async.cg.shared.global [%0], [%1], 16;"
                 :: "r"(dst), "l"(src) : "memory");
}
__device__ __forceinline__ void cp_commit() {
    asm volatile("cp.async.commit_group;" ::: "memory");
}
__device__ __forceinline__ void cp_wait0() {
    asm volatile("cp.async.wait_group 0;" ::: "memory");
}
__device__ __forceinline__ void mma_f16(float* c, const u32* a, u32 b0, u32 b1) {
    asm volatile(
        "mma.sync.aligned.m16n8k16.row.col.f32.f16.f16.f32 "
        "{%0,%1,%2,%3}, {%4,%5,%6,%7}, {%8,%9}, {%0,%1,%2,%3};"
        : "+f"(c[0]), "+f"(c[1]), "+f"(c[2]), "+f"(c[3])
        : "r"(a[0]), "r"(a[1]), "r"(a[2]), "r"(a[3]), "r"(b0), "r"(b1));
}
__device__ __forceinline__ void ldsm_x4(u32& r0, u32& r1, u32& r2, u32& r3, u32 a) {
    asm volatile("ldmatrix.sync.aligned.m8n8.x4.shared.b16 {%0,%1,%2,%3}, [%4];"
        : "=r"(r0), "=r"(r1), "=r"(r2), "=r"(r3) : "r"(a));
}

// ---------------------------------------------------------------------------
// prep: zero counts/flags, ||c||^2 (fp32), codebook -> fp16
// ---------------------------------------------------------------------------
__global__ void prep_kernel(const float* __restrict__ cb) {
    int gtid = blockIdx.x * blockDim.x + threadIdx.x;
    if (gtid < KCODES) d_counts[gtid] = 0.0f;
    if (gtid == 0) d_flagCount = 0;
    int w = gtid >> 5;
    int lane = threadIdx.x & 31;
    if (w < KCODES) {
        const float* r = cb + (size_t)w * DIMS;
        float s = 0.0f;
        #pragma unroll
        for (int i = 0; i < DIMS / 32; i++) {
            int d = lane + i * 32;
            float v = r[d];
            s = fmaf(v, v, s);
            d_cbh[(size_t)w * DIMS + d] = __float2half(v);
        }
        #pragma unroll
        for (int off = 16; off > 0; off >>= 1)
            s += __shfl_xor_sync(0xFFFFFFFFu, s, off);
        if (lane == 0) d_cnorm[w] = s;
    }
}

// ---------------------------------------------------------------------------
// main: fp16 HMMA GEMM (ldmatrix fragments) + top-2 + flag + gather + hist
// (byte-identical to the 310us champion)
// ---------------------------------------------------------------------------
__global__ __launch_bounds__(NTHREADS, 1)
void vq_kernel(const float* __restrict__ z, const float* __restrict__ cb,
               float* __restrict__ out) {
    extern __shared__ char raw[];
    char* dsm = (char*)(((uintptr_t)raw + 1023) & ~(uintptr_t)1023);
    char* Ab = dsm;                         // 66 KB z fp16, resident
    char* Bb = dsm + A_BYTES;               // 2 x 18 KB B buffers
    float* redV1 = (float*)Bb;              // aliases B bufs post-GEMM
    float* redV2 = redV1 + BM * 16;
    int*   redI  = (int*)(redV2 + BM * 16);
    __shared__ int sIdx[BM];

    const int tid = threadIdx.x;
    const int lane = tid & 31;
    const int wid = tid >> 5;               // 0..15
    const int warpRow = wid & 3;            // 4 row-warps x 32 rows
    const int warpCol = wid >> 2;           // 4 col-warps x 32 cols
    const int g = lane >> 2;                // 0..7
    const int tig = lane & 3;               // 0..3
    const int rowBase = blockIdx.x * BM;
    const u32 A_u32 = smem_u32(Ab);
    const u32 B_u32 = smem_u32(Bb);

    for (int i = tid; i < BM * 128; i += NTHREADS) {
        int r = i >> 7, d2 = i & 127;
        float2 f = ((const float2*)(z + (size_t)(rowBase + r) * DIMS))[d2];
        __half h0 = __float2half(f.x);
        __half h1 = __float2half(f.y);
        u32 uh = (u32)__half_as_ushort(h0) | ((u32)__half_as_ushort(h1) << 16);
        *(u32*)(Ab + r * A_ROW_B + d2 * 4) = uh;
    }
    __syncthreads();

    float best1[4], best2[4];
    int idx1[4];
    #pragma unroll
    for (int i = 0; i < 4; i++) { best1[i] = 3.4e38f; best2[i] = 3.4e38f; idx1[i] = 0; }

    const u32 aLane = A_u32 + (warpRow * 32 + (lane & 15)) * A_ROW_B
                            + ((lane & 16) ? 16 : 0);
    const u32 bLane = B_u32 + (warpCol * 32 + (lane & 7) + ((lane & 16) ? 8 : 0)) * B_ROW_B
                            + ((lane & 8) ? 16 : 0);

    const int bRow = tid >> 2;
    const int part = tid & 3;

    for (int chnk = 0; chnk < KCODES / BN; chnk++) {
        float acc[2][4][4];
        #pragma unroll
        for (int mf = 0; mf < 2; mf++)
            #pragma unroll
            for (int nf = 0; nf < 4; nf++)
                #pragma unroll
                for (int q = 0; q < 4; q++) acc[mf][nf][q] = 0.0f;

        const __half* gRow = d_cbh + (size_t)(chnk * BN + bRow) * DIMS + part * 16;
        const u32 dstBase = B_u32 + bRow * B_ROW_B + part * 32;

        cpasync16(dstBase, gRow);
        cpasync16(dstBase + 16, gRow + 8);
        cp_commit();

        #pragma unroll
        for (int s = 0; s < 4; s++) {
            cp_wait0();
            __syncthreads();
            if (s < 3) {
                const __half* src = gRow + (s + 1) * 64;
                u32 dst = dstBase + (((s + 1) & 1) ? B_CHUNKB : 0);
                cpasync16(dst, src);
                cpasync16(dst + 16, src + 8);
                cp_commit();
            }
            const u32 aS = aLane + s * 128;
            const u32 bS = bLane + ((s & 1) ? B_CHUNKB : 0);
            #pragma unroll
            for (int kk = 0; kk < 4; kk++) {
                u32 a0[4], a1[4], bA[4], bB[4];
                ldsm_x4(a0[0], a0[1], a0[2], a0[3], aS + kk * 32);
                ldsm_x4(a1[0], a1[1], a1[2], a1[3], aS + 16 * A_ROW_B + kk * 32);
                ldsm_x4(bA[0], bA[1], bA[2], bA[3], bS + kk * 32);
                ldsm_x4(bB[0], bB[1], bB[2], bB[3], bS + 16 * B_ROW_B + kk * 32);
                mma_f16(acc[0][0], a0, bA[0], bA[1]);
                mma_f16(acc[1][0], a1, bA[0], bA[1]);
                mma_f16(acc[0][1], a0, bA[2], bA[3]);
                mma_f16(acc[1][1], a1, bA[2], bA[3]);
                mma_f16(acc[0][2], a0, bB[0], bB[1]);
                mma_f16(acc[1][2], a1, bB[0], bB[1]);
                mma_f16(acc[0][3], a0, bB[2], bB[3]);
                mma_f16(acc[1][3], a1, bB[2], bB[3]);
            }
        }

        #pragma unroll
        for (int nf = 0; nf < 4; nf++) {
            #pragma unroll
            for (int cc = 0; cc < 2; cc++) {
                int col = chnk * BN + warpCol * 32 + nf * 8 + tig * 2 + cc;
                float cn = __ldg(&d_cnorm[col]);
                #pragma unroll
                for (int mf = 0; mf < 2; mf++) {
                    #pragma unroll
                    for (int sub = 0; sub < 2; sub++) {
                        float cost = fmaf(-2.0f, acc[mf][nf][sub * 2 + cc], cn);
                        int rr = mf * 2 + sub;
                        if (cost < best1[rr]) {
                            best2[rr] = best1[rr];
                            best1[rr] = cost; idx1[rr] = col;
                        } else if (cost < best2[rr]) {
                            best2[rr] = cost;
                        }
                    }
                }
            }
        }
    }

    __syncthreads();

    const int slot = warpCol * 4 + tig;
    #pragma unroll
    for (int rr = 0; rr < 4; rr++) {
        int r = warpRow * 32 + (rr >> 1) * 16 + (rr & 1) * 8 + g;
        redV1[r * 16 + slot] = best1[rr];
        redV2[r * 16 + slot] = best2[rr];
        redI[r * 16 + slot] = idx1[rr];
    }
    __syncthreads();

    if (tid < BM) {
        float b1 = 3.4e38f, b2 = 3.4e38f;
        int i1 = 0x7FFFFFFF;
        #pragma unroll
        for (int t = 0; t < 16; t++) {
            float v1 = redV1[tid * 16 + t];
            float v2 = redV2[tid * 16 + t];
            int ix = redI[tid * 16 + t];
            if (v1 < b1) {
                b2 = fminf(b1, v2);
                b1 = v1; i1 = ix;
            } else if (v1 == b1) {
                i1 = min(i1, ix);
                b2 = fminf(b2, v2);
            } else {
                b2 = fminf(b2, fminf(v1, v2));
            }
        }
        sIdx[tid] = i1;
        d_idx[rowBase + tid] = i1;
        atomicAdd(&d_counts[i1], 1.0f);
        if (b2 - b1 < MARGIN) {
            int p = atomicAdd(&d_flagCount, 1);
            d_flagList[p] = rowBase + tid;
        }
    }
    __syncthreads();

    const float4* cb4 = (const float4*)cb;
    float4* out4 = (float4*)out;
    for (int i = tid; i < BM * 64; i += NTHREADS) {
        int r = i >> 6, q = i & 63;
        int code = sIdx[r];
        out4[(size_t)(rowBase + r) * 64 + q] = cb4[(size_t)code * 64 + q];
    }
}

// ---------------------------------------------------------------------------
// rescan v2: exact fp32, 16 rows/block, ILP-restructured:
// q-outer, 4 independent code chains, dot[4][8] register block, cv prefetch
// ---------------------------------------------------------------------------
__global__ __launch_bounds__(256)
void rescan_kernel(const float* __restrict__ z,
                   const float* __restrict__ cb,
                   float* __restrict__ out) {
    __shared__ float zr[16][DIMS];
    __shared__ float sRV[16][8];
    __shared__ int   sRI[16][8];
    __shared__ int   sRow[16];
    __shared__ int   sFix[16];

    const int tid = threadIdx.x;
    const int lane = tid & 31;
    const int wrp = tid >> 5;
    const int cnt = d_flagCount;

    for (int base = blockIdx.x * 16; base < cnt; base += gridDim.x * 16) {
        const int nr = min(16, cnt - base);
        for (int i = tid; i < 16 * DIMS; i += 256)
            ((float*)zr)[i] = 0.0f;
        __syncthreads();
        if (tid < nr) sRow[tid] = d_flagList[base + tid];
        __syncthreads();
        for (int i = tid; i < nr * DIMS; i += 256)
            zr[i >> 8][i & 255] = z[(size_t)sRow[i >> 8] * DIMS + (i & 255)];
        __syncthreads();

        float bb[16]; int bi[16];
        #pragma unroll
        for (int r = 0; r < 16; r++) { bb[r] = 3.4e38f; bi[r] = 0x7FFFFFFF; }

        // code pointers: 4 independent chains, codes tid + cc*256
        const float4* cp0 = (const float4*)(cb + (size_t)(tid + 0)   * DIMS);
        const float4* cp1 = (const float4*)(cb + (size_t)(tid + 256) * DIMS);
        const float4* cp2 = (const float4*)(cb + (size_t)(tid + 512) * DIMS);
        const float4* cp3 = (const float4*)(cb + (size_t)(tid + 768) * DIMS);

        #pragma unroll
        for (int pass = 0; pass < 2; pass++) {
            float dot[4][8];
            #pragma unroll
            for (int c4 = 0; c4 < 4; c4++)
                #pragma unroll
                for (int r = 0; r < 8; r++) dot[c4][r] = 0.0f;

            float4 cv0 = cp0[0], cv1 = cp1[0], cv2 = cp2[0], cv3 = cp3[0];
            #pragma unroll 4
            for (int q = 0; q < 64; q++) {
                float4 nv0, nv1, nv2, nv3;
                if (q < 63) {
                    nv0 = cp0[q + 1]; nv1 = cp1[q + 1];
                    nv2 = cp2[q + 1]; nv3 = cp3[q + 1];
                }
                #pragma unroll
                for (int r = 0; r < 8; r++) {
                    float4 zv = *(const float4*)&zr[pass * 8 + r][q * 4];
                    dot[0][r] = fmaf(zv.x, cv0.x, dot[0][r]);
                    dot[0][r] = fmaf(zv.y, cv0.y, dot[0][r]);
                    dot[0][r] = fmaf(zv.z, cv0.z, dot[0][r]);
                    dot[0][r] = fmaf(zv.w, cv0.w, dot[0][r]);
                    dot[1][r] = fmaf(zv.x, cv1.x, dot[1][r]);
                    dot[1][r] = fmaf(zv.y, cv1.y, dot[1][r]);
                    dot[1][r] = fmaf(zv.z, cv1.z, dot[1][r]);
                    dot[1][r] = fmaf(zv.w, cv1.w, dot[1][r]);
                    dot[2][r] = fmaf(zv.x, cv2.x, dot[2][r]);
                    dot[2][r] = fmaf(zv.y, cv2.y, dot[2][r]);
                    dot[2][r] = fmaf(zv.z, cv2.z, dot[2][r]);
                    dot[2][r] = fmaf(zv.w, cv2.w, dot[2][r]);
                    dot[3][r] = fmaf(zv.x, cv3.x, dot[3][r]);
                    dot[3][r] = fmaf(zv.y, cv3.y, dot[3][r]);
                    dot[3][r] = fmaf(zv.z, cv3.z, dot[3][r]);
                    dot[3][r] = fmaf(zv.w, cv3.w, dot[3][r]);
                }
                cv0 = nv0; cv1 = nv1; cv2 = nv2; cv3 = nv3;
            }

            #pragma unroll
            for (int c4 = 0; c4 < 4; c4++) {
                const int c = tid + c4 * 256;
                const float cn = __ldg(&d_cnorm[c]);
                #pragma unroll
                for (int r = 0; r < 8; r++) {
                    float cost = fmaf(-2.0f, dot[c4][r], cn);
                    int rr = pass * 8 + r;
                    if (cost < bb[rr] || (cost == bb[rr] && c < bi[rr])) {
                        bb[rr] = cost; bi[rr] = c;
                    }
                }
            }
        }

        #pragma unroll
        for (int off = 16; off > 0; off >>= 1) {
            #pragma unroll
            for (int r = 0; r < 16; r++) {
                float vv = __shfl_xor_sync(0xFFFFFFFFu, bb[r], off);
                int ii = __shfl_xor_sync(0xFFFFFFFFu, bi[r], off);
                if (vv < bb[r] || (vv == bb[r] && ii < bi[r])) { bb[r] = vv; bi[r] = ii; }
            }
        }
        if (lane == 0) {
            #pragma unroll
            for (int r = 0; r < 16; r++) { sRV[r][wrp] = bb[r]; sRI[r][wrp] = bi[r]; }
        }
        __syncthreads();
        if (tid < nr) {
            float bv = 3.4e38f; int bix = 0x7FFFFFFF;
            #pragma unroll
            for (int w = 0; w < 8; w++) {
                float v = sRV[tid][w]; int ix = sRI[tid][w];
                if (v < bv || (v == bv && ix < bix)) { bv = v; bix = ix; }
            }
            int old = d_idx[sRow[tid]];
            sFix[tid] = bix;
            if (bix != old) {
                d_idx[sRow[tid]] = bix;
                atomicAdd(&d_counts[old], -1.0f);
                atomicAdd(&d_counts[bix], 1.0f);
            }
        }
        __syncthreads();
        const float4* cb4 = (const float4*)cb;
        float4* out4 = (float4*)out;
        for (int i = tid; i < nr * 64; i += 256) {
            int r = i >> 6, q = i & 63;
            out4[(size_t)sRow[r] * 64 + q] = cb4[(size_t)sFix[r] * 64 + q];
        }
        __syncthreads();
    }
}

// ---------------------------------------------------------------------------
__global__ void perp_kernel(float* __restrict__ out, int nd, float n) {
    __shared__ float s[KCODES];
    int t = threadIdx.x;
    float e = d_counts[t] / n;
    s[t] = e * logf(e + 1e-10f);
    __syncthreads();
    for (int st = KCODES / 2; st > 0; st >>= 1) {
        if (t < st) s[t] += s[t + st];
        __syncthreads();
    }
    if (t == 0) {
        out[nd] = 0.0f;
        out[nd + 1] = expf(-s[0]);
    }
}

extern "C" void kernel_launch(void* const* d_in, const int* in_sizes, int n_in,
                              void* d_out, int out_size) {
    const float* z = (const float*)d_in[0];
    const float* cb = (const float*)d_in[1];
    float* out = (float*)d_out;

    int nrows = in_sizes[0] / DIMS;  // 65536
    cudaFuncSetAttribute(vq_kernel, cudaFuncAttributeMaxDynamicSharedMemorySize,
                         DSMEM_BYTES);
    prep_kernel<<<128, 256>>>(cb);
    vq_kernel<<<nrows / BM, NTHREADS, DSMEM_BYTES>>>(z, cb, out);
    rescan_kernel<<<296, 256>>>(z, cb, out);
    long nd = (long)nrows * DIMS;
    if ((long)out_size >= nd + 2)
        perp_kernel<<<1, KCODES>>>(out, (int)nd, (float)nrows);
}